// round 15
// baseline (speedup 1.0000x reference)
#include <cuda_runtime.h>
#include <math.h>
#include <stdint.h>

#define N_ROWS 8192
#define DIM    512
#define NCLS   10
#define NMAT   32
#define PNB    64

// ---------------- scratch (static device globals; no allocation) ----------------
__device__ int    g_counts[NCLS];
__device__ int    g_offsets[NCLS];
__device__ int    g_sorted[N_ROWS];
__device__ float  g_gram[2 * NCLS][DIM * DIM];
__device__ float  g_M[NMAT][DIM * DIM];
__device__ float  g_P[NMAT][(DIM - PNB) * PNB];
__device__ float  g_W[NMAT][PNB * PNB];
__device__ int    g_fT[NMAT * 8];          // TRSM done flag per global tile row (monotone = p+1)
__device__ double g_logdet[NMAT];

// ---------------- fused setup ----------------
__global__ void __launch_bounds__(1024) k_setup(const int* __restrict__ lbl) {
    __shared__ int sc[NCLS], scur[NCLS];
    int tid = threadIdx.x;
    if (tid < NCLS) sc[tid] = 0;
    if (tid < NMAT) g_logdet[tid] = 0.0;
    if (tid < NMAT * 8) g_fT[tid] = 0;
    __syncthreads();
    for (int i = tid; i < N_ROWS; i += 1024) atomicAdd(&sc[lbl[i]], 1);
    __syncthreads();
    if (tid == 0) {
        int acc = 0;
        for (int c = 0; c < NCLS; c++) {
            g_counts[c]  = sc[c];
            g_offsets[c] = acc;
            scur[c] = acc;
            acc += sc[c];
        }
    }
    __syncthreads();
    for (int i = tid; i < N_ROWS; i += 1024) {
        int p = atomicAdd(&scur[lbl[i]], 1);
        g_sorted[p] = i;
    }
}

// ---------------- cp.async helper ----------------
__device__ __forceinline__ void cpa16(uint32_t dst, const void* src, int sz) {
    asm volatile("cp.async.ca.shared.global [%0], [%1], 16, %2;"
                 :: "r"(dst), "l"(src), "r"(sz));
}

// ---------------- per-class Gram (validated) ----------------
__global__ void __launch_bounds__(64) k_gram(const float* __restrict__ Z,
                                             const float* __restrict__ Zb) {
    int m = blockIdx.y;
    int c = m % NCLS;
    const float* src = (m < NCLS) ? Z : Zb;

    int bi = 0, r = blockIdx.x;
    while (r >= bi + 1) { r -= bi + 1; bi++; }
    int bj = r;

    int off = g_offsets[c];
    int cnt = g_counts[c];

    __shared__ __align__(16) float sA[2][32][64];
    __shared__ __align__(16) float sB[2][32][64];

    int tid = threadIdx.x;
    int tx = tid & 7, ty = tid >> 3;
    int q = tid & 15;
    int kbase = tid >> 4;

    uint32_t sA0 = (uint32_t)__cvta_generic_to_shared(&sA[0][0][0]);
    uint32_t sB0 = (uint32_t)__cvta_generic_to_shared(&sB[0][0][0]);

    int nC = (cnt + 31) >> 5;

    auto issue = [&](int ci, int b) {
#pragma unroll
        for (int it = 0; it < 8; it++) {
            int k  = kbase + it * 4;
            int kr = ci * 32 + k;
            const float* pa = src;
            const float* pb = src;
            int sz = 0;
            if (kr < cnt) {
                int row = g_sorted[off + kr];
                const float* rp = src + (size_t)row * DIM;
                pa = rp + bi * 64 + q * 4;
                pb = rp + bj * 64 + q * 4;
                sz = 16;
            }
            uint32_t o = (uint32_t)(((b * 32 + k) * 64 + q * 4) * 4);
            cpa16(sA0 + o, pa, sz);
            cpa16(sB0 + o, pb, sz);
        }
        asm volatile("cp.async.commit_group;");
    };

    float acc[8][8];
#pragma unroll
    for (int i = 0; i < 8; i++)
#pragma unroll
        for (int j = 0; j < 8; j++) acc[i][j] = 0.f;

    if (nC > 0) issue(0, 0);
    for (int ci = 0; ci < nC; ci++) {
        int b = ci & 1;
        asm volatile("cp.async.wait_group 0;" ::: "memory");
        __syncthreads();
        if (ci + 1 < nC) issue(ci + 1, b ^ 1);

#pragma unroll 8
        for (int k = 0; k < 32; k++) {
            float4 a0 = *(const float4*)&sA[b][k][ty * 8];
            float4 a1 = *(const float4*)&sA[b][k][ty * 8 + 4];
            float4 b0 = *(const float4*)&sB[b][k][tx * 8];
            float4 b1 = *(const float4*)&sB[b][k][tx * 8 + 4];
            float aa[8] = {a0.x, a0.y, a0.z, a0.w, a1.x, a1.y, a1.z, a1.w};
            float bb[8] = {b0.x, b0.y, b0.z, b0.w, b1.x, b1.y, b1.z, b1.w};
#pragma unroll
            for (int i = 0; i < 8; i++)
#pragma unroll
                for (int j = 0; j < 8; j++) acc[i][j] += aa[i] * bb[j];
        }
        __syncthreads();
    }

    float* G = g_gram[m];
#pragma unroll
    for (int i = 0; i < 8; i++) {
        int gi = bi * 64 + ty * 8 + i;
        float4 v0 = make_float4(acc[i][0], acc[i][1], acc[i][2], acc[i][3]);
        float4 v1 = make_float4(acc[i][4], acc[i][5], acc[i][6], acc[i][7]);
        int gj = bj * 64 + tx * 8;
        *(float4*)&G[(size_t)gi * DIM + gj]     = v0;
        *(float4*)&G[(size_t)gi * DIM + gj + 4] = v1;
        if (bi != bj) {
#pragma unroll
            for (int j = 0; j < 8; j++)
                G[(size_t)(gj + j) * DIM + gi] = acc[i][j];
        }
    }
}

// ---------------- build the 32 matrices M = I + s*G ----------------
__global__ void __launch_bounds__(128) k_buildM() {
    int m   = blockIdx.y;
    int row = blockIdx.x;
    int col = threadIdx.x * 4;

    float4 v;
    if (m < 20) {
        int c = (m < 10) ? m : (m - 10);
        float cnt = (float)g_counts[c];
        float s = 512.f / ((cnt + 1e-8f) * 0.5f);
        float4 g = *(const float4*)&g_gram[m][row * DIM + col];
        v = make_float4(s * g.x, s * g.y, s * g.z, s * g.w);
    } else if (m < 30) {
        int c = m - 20;
        float cnt = (float)g_counts[c];
        float s = 512.f / (2.f * cnt * 0.5f);
        float4 g1 = *(const float4*)&g_gram[c][row * DIM + col];
        float4 g2 = *(const float4*)&g_gram[10 + c][row * DIM + col];
        v = make_float4(s * (g1.x + g2.x), s * (g1.y + g2.y),
                        s * (g1.z + g2.z), s * (g1.w + g2.w));
    } else {
        int base = (m == 30) ? 0 : 10;
        float4 s4 = make_float4(0.f, 0.f, 0.f, 0.f);
        for (int c = 0; c < NCLS; c++) {
            float4 g = *(const float4*)&g_gram[base + c][row * DIM + col];
            s4.x += g.x; s4.y += g.y; s4.z += g.z; s4.w += g.w;
        }
        const float s = 0.125f;
        v = make_float4(s * s4.x, s * s4.y, s * s4.z, s * s4.w);
    }
    if (row >= col && row < col + 4) {
        if (row == col)          v.x += 1.f;
        else if (row == col + 1) v.y += 1.f;
        else if (row == col + 2) v.z += 1.f;
        else                     v.w += 1.f;
    }
    *(float4*)&g_M[m][row * DIM + col] = v;
}

// ---------------- standalone diag (panel 0 only) — R13 validated ----------------
__global__ void __launch_bounds__(256) k_diag64(int kb) {
    int m = blockIdx.x;
    float* M = g_M[m];

    __shared__ float  sL[64][65];
    __shared__ __align__(16) float sW[64][68];
    __shared__ float  sT[32][33];
    __shared__ float  sColB[2][64];
    __shared__ float  sInv[64];
    __shared__ double sRed[8];

    int tid = threadIdx.x;
    int r  = tid & 63;
    int s  = tid >> 6;
    int c0 = s * 16;

    float a[16];
    {
        const float* rp = M + (size_t)(kb + r) * DIM + kb + c0;
#pragma unroll
        for (int t4 = 0; t4 < 4; t4++) {
            float4 v = *(const float4*)(rp + t4 * 4);
            a[t4*4+0]=v.x; a[t4*4+1]=v.y; a[t4*4+2]=v.z; a[t4*4+3]=v.w;
        }
    }
    if (s == 0) sColB[0][r] = a[0];
    __syncthreads();

    double lsum = 0.0;
    for (int j = 0; j < 64; j++) {
        int par = j & 1;
        float d  = sColB[par][j];
        float rs = rsqrtf(d);
        float t2 = sColB[par][r] * (rs * rs);
#pragma unroll
        for (int i = 0; i < 16; i++) {
            int c = c0 + i;
            if (c > j) a[i] -= t2 * sColB[par][c];
        }
        if (s == (j >> 4)) sL[r][j] = sColB[par][r] * rs;
        if (j < 63 && s == ((j + 1) >> 4)) sColB[par ^ 1][r] = a[(j + 1) & 15];
        if (tid == j) { sInv[j] = rs; lsum = (double)logf(d); }
        __syncthreads();
    }

#pragma unroll
    for (int o = 16; o; o >>= 1) lsum += __shfl_xor_sync(0xffffffffu, lsum, o);
    if ((tid & 31) == 0) sRed[tid >> 5] = lsum;
    __syncthreads();
    if (tid == 0) {
        double s2 = 0.0;
        for (int i = 0; i < 8; i++) s2 += sRed[i];
        g_logdet[m] += s2;
    }

    for (int e = tid; e < 64 * 68; e += 256)
        ((float*)sW)[e] = 0.f;
    __syncthreads();

    if (tid < 64) {
        int base = (tid < 32) ? 0 : 32;
        int c = tid & 31;
        float w[32], prt[32];
#pragma unroll
        for (int t = 0; t < 32; t++) prt[t] = 0.f;
#pragma unroll
        for (int j = 0; j < 32; j++) {
            float v;
            if (j < c)       v = 0.f;
            else if (j == c) v = sInv[base + j];
            else             v = -prt[j] * sInv[base + j];
            w[j] = v;
#pragma unroll
            for (int j2 = 0; j2 < 32; j2++)
                if (j2 > j) prt[j2] += sL[base + j2][base + j] * v;
        }
#pragma unroll
        for (int j = 0; j < 32; j++) sW[base + j][base + c] = w[j];
    }
    __syncthreads();

    for (int e = tid; e < 1024; e += 256) {
        int i = e >> 5, j = e & 31;
        float acc = 0.f;
#pragma unroll
        for (int t = 0; t < 32; t++) acc += sL[32 + i][t] * sW[t][j];
        sT[i][j] = acc;
    }
    __syncthreads();

    for (int e = tid; e < 1024; e += 256) {
        int i = e >> 5, j = e & 31;
        float acc = 0.f;
#pragma unroll
        for (int t = 0; t < 32; t++) acc += sW[32 + i][32 + t] * sT[t][j];
        sW[32 + i][j] = -acc;
    }
    __syncthreads();

#pragma unroll
    for (int it = 0; it < 4; it++) {
        int t = tid + it * 256;
        int rr = t >> 4, q = t & 15;
        *(float4*)(g_W[m] + rr * PNB + q * 4) = *(const float4*)&sW[rr][q * 4];
    }
}

// ---------------- fused panel: TRSM blocks + flag-gated SYRK blocks + embedded diag ----------------
// grid = (nt + nt*(nt+1)/2, NMAT), 64 threads.
//  blocks [0, nt):    TRSM tile ti -> P, then flag g_fT[m*8 + (p+1+ti)] = p+1
//  blocks [nt, ...):  SYRK pair (ti,tj); spin until both row flags >= p+1.
//                     First SYRK block (tile (0,0)) embeds next-panel diag (R14 validated).
__global__ void __launch_bounds__(64) k_panel(int kb, int last) {
    __shared__ __align__(16) float pool[9984];
    float (*sA)[65] = (float(*)[65])pool;              // scalar access only
    float (*sB)[65] = (float(*)[65])(pool + 4160);     // scalar access only

    int p  = kb / PNB;
    int nt = 7 - p;
    int m  = blockIdx.y;
    float* M = g_M[m];
    float* P = g_P[m];
    int tid = threadIdx.x;
    int tx = tid & 7, ty = tid >> 3;
    int base = kb + PNB;

    if (blockIdx.x < nt) {
        // ================= TRSM role: P(tile ti) = A21 * W^T =================
        int ti = blockIdx.x;
        const float* W = g_W[m];

#pragma unroll
        for (int it = 0; it < 16; it++) {
            int t = tid + it * 64;
            int row = t >> 4, q = t & 15;
            float4 va = *(const float4*)(M + (size_t)(base + ti * 64 + row) * DIM + kb + q * 4);
            sA[row][q*4+0]=va.x; sA[row][q*4+1]=va.y; sA[row][q*4+2]=va.z; sA[row][q*4+3]=va.w;
            float4 vb = *(const float4*)(W + row * PNB + q * 4);
            sB[row][q*4+0]=vb.x; sB[row][q*4+1]=vb.y; sB[row][q*4+2]=vb.z; sB[row][q*4+3]=vb.w;
        }
        __syncthreads();

        float acc[8][8];
#pragma unroll
        for (int i = 0; i < 8; i++)
#pragma unroll
            for (int j = 0; j < 8; j++) acc[i][j] = 0.f;

#pragma unroll 4
        for (int k = 0; k < PNB; k++) {
            float aa[8], bb[8];
#pragma unroll
            for (int i = 0; i < 8; i++) aa[i] = sA[ty * 8 + i][k];
#pragma unroll
            for (int j = 0; j < 8; j++) bb[j] = sB[tx * 8 + j][k];
#pragma unroll
            for (int i = 0; i < 8; i++)
#pragma unroll
                for (int j = 0; j < 8; j++) acc[i][j] += aa[i] * bb[j];
        }

#pragma unroll
        for (int i = 0; i < 8; i++) {
            int rl = ti * 64 + ty * 8 + i;
            float* pp = P + (size_t)rl * PNB + tx * 8;
            *(float4*)pp       = make_float4(acc[i][0], acc[i][1], acc[i][2], acc[i][3]);
            *(float4*)(pp + 4) = make_float4(acc[i][4], acc[i][5], acc[i][6], acc[i][7]);
        }
        __threadfence();
        __syncthreads();
        if (tid == 0) atomicExch(&g_fT[m * 8 + p + 1 + ti], p + 1);
        return;
    }

    // ================= SYRK role =================
    int t2 = blockIdx.x - nt;
    int ti = 0, rr = t2;
    while (rr >= ti + 1) { rr -= ti + 1; ti++; }
    int tj = rr;

    // wait for needed P tiles
    if (tid == 0) {
        volatile int* fI = &g_fT[m * 8 + p + 1 + ti];
        volatile int* fJ = &g_fT[m * 8 + p + 1 + tj];
        while (*fI < p + 1) { }
        while (*fJ < p + 1) { }
    }
    __syncthreads();

#pragma unroll
    for (int it = 0; it < 16; it++) {
        int t = tid + it * 64;
        int row = t >> 4, q = t & 15;
        int ra = ti * 64 + row;
        float4 va = __ldcg((const float4*)(P + (size_t)ra * PNB + q * 4));
        sA[row][q*4+0]=va.x; sA[row][q*4+1]=va.y; sA[row][q*4+2]=va.z; sA[row][q*4+3]=va.w;
        int rb = tj * 64 + row;
        float4 vb = __ldcg((const float4*)(P + (size_t)rb * PNB + q * 4));
        sB[row][q*4+0]=vb.x; sB[row][q*4+1]=vb.y; sB[row][q*4+2]=vb.z; sB[row][q*4+3]=vb.w;
    }
    __syncthreads();

    float acc[8][8];
#pragma unroll
    for (int i = 0; i < 8; i++)
#pragma unroll
        for (int j = 0; j < 8; j++) acc[i][j] = 0.f;

#pragma unroll 4
    for (int k = 0; k < PNB; k++) {
        float aa[8], bb[8];
#pragma unroll
        for (int i = 0; i < 8; i++) aa[i] = sA[ty * 8 + i][k];
#pragma unroll
        for (int j = 0; j < 8; j++) bb[j] = sB[tx * 8 + j][k];
#pragma unroll
        for (int i = 0; i < 8; i++)
#pragma unroll
            for (int j = 0; j < 8; j++) acc[i][j] += aa[i] * bb[j];
    }

    if (t2 != 0) {
        if (ti != tj) {
#pragma unroll
            for (int i = 0; i < 8; i++) {
                int rl = ti * 64 + ty * 8 + i;
                float* mp = M + (size_t)(base + rl) * DIM + base + tj * 64 + tx * 8;
                float4 v0 = *(float4*)mp;
                float4 v1 = *(float4*)(mp + 4);
                v0.x -= acc[i][0]; v0.y -= acc[i][1]; v0.z -= acc[i][2]; v0.w -= acc[i][3];
                v1.x -= acc[i][4]; v1.y -= acc[i][5]; v1.z -= acc[i][6]; v1.w -= acc[i][7];
                *(float4*)mp = v0;
                *(float4*)(mp + 4) = v1;
            }
        } else {
#pragma unroll
            for (int i = 0; i < 8; i++) {
                int rl = ti * 64 + ty * 8 + i;
                float* mp = M + (size_t)(base + rl) * DIM + base;
#pragma unroll
                for (int j = 0; j < 8; j++) {
                    int cl = tj * 64 + tx * 8 + j;
                    if (cl <= rl) mp[cl] -= acc[i][j];
                }
            }
        }
        return;
    }

    // ============ first SYRK block: diag tile update into SMEM + factor (R14 validated) ============
    __syncthreads();
    float (*sD)[65] = (float(*)[65])pool;
#pragma unroll
    for (int i = 0; i < 8; i++) {
        int rl = ty * 8 + i;
        const float* mp = M + (size_t)(base + rl) * DIM + base;
#pragma unroll
        for (int j = 0; j < 8; j++) {
            int cl = tx * 8 + j;
            if (cl <= rl) sD[rl][cl] = mp[cl] - acc[i][j];
        }
    }
    __syncthreads();

    int r = tid;
    float a[64];
#pragma unroll
    for (int c = 0; c < 64; c++) a[c] = sD[r][c];
    __syncthreads();

    float* sColBuf = pool + 9760;
    float* sInv    = pool + 9888;
    double* sRed   = (double*)(pool + 9952);

    double lsum = 0.0;
#pragma unroll
    for (int j = 0; j < 64; j++) {
        float* sCol = sColBuf + (j & 1) * 64;
        sCol[r] = a[j];
        __syncthreads();
        float d   = sCol[j];
        float inv = rsqrtf(d);
        if (r == j) { lsum = (double)logf(d); sInv[j] = inv; }
        a[j] *= inv;
        float t = a[j] * inv;
#pragma unroll
        for (int c = j + 1; c < 64; c++)
            a[c] -= t * sCol[c];
    }

#pragma unroll
    for (int o = 16; o; o >>= 1) lsum += __shfl_xor_sync(0xffffffffu, lsum, o);
    if ((r & 31) == 0) sRed[r >> 5] = lsum;
    __syncthreads();
    if (r == 0) g_logdet[m] += sRed[0] + sRed[1];

    if (last) return;

    float (*sL)[68] = (float(*)[68])pool;
    float (*sW)[68] = (float(*)[68])(pool + 4352);
    float (*sT)[33] = (float(*)[33])(pool + 8704);
#pragma unroll
    for (int t4 = 0; t4 < 16; t4++)
        *(float4*)&sL[r][t4*4] =
            make_float4(a[t4*4], a[t4*4+1], a[t4*4+2], a[t4*4+3]);
    __syncthreads();

    {
        int base2 = (r < 32) ? 0 : 32;
        int c = r & 31;
        float w[32], prt[32];
#pragma unroll
        for (int t = 0; t < 32; t++) prt[t] = 0.f;
#pragma unroll
        for (int j = 0; j < 32; j++) {
            float v;
            if (j < c)       v = 0.f;
            else if (j == c) v = sInv[base2 + j];
            else             v = -prt[j] * sInv[base2 + j];
            w[j] = v;
#pragma unroll
            for (int j2 = 0; j2 < 32; j2++)
                if (j2 > j) prt[j2] += sL[base2 + j2][base2 + j] * v;
        }
#pragma unroll
        for (int j = 0; j < 32; j++) sW[base2 + j][base2 + c] = w[j];
    }
    if (r < 32) {
        float4 z = make_float4(0.f, 0.f, 0.f, 0.f);
#pragma unroll
        for (int t4 = 8; t4 < 16; t4++) *(float4*)&sW[r][t4*4] = z;
    }
    __syncthreads();

    for (int e = r; e < 1024; e += 64) {
        int i = e >> 5, j = e & 31;
        float s = 0.f;
#pragma unroll
        for (int t = 0; t < 32; t++) s += sL[32 + i][t] * sW[t][j];
        sT[i][j] = s;
    }
    __syncthreads();

    for (int e = r; e < 1024; e += 64) {
        int i = e >> 5, j = e & 31;
        float s = 0.f;
#pragma unroll
        for (int t = 0; t < 32; t++) s += sW[32 + i][32 + t] * sT[t][j];
        sW[32 + i][j] = -s;
    }
    __syncthreads();

    {
        float* wp = g_W[m] + r * PNB;
#pragma unroll
        for (int t4 = 0; t4 < 16; t4++)
            *(float4*)(wp + t4 * 4) = *(const float4*)&sW[r][t4*4];
    }
}

// ---------------- combine into the 4 outputs ----------------
__global__ void k_combine(float* __restrict__ out) {
    if (threadIdx.x == 0) {
        double sum_ldz = 0.0, sum_ldzb = 0.0, comp_z = 0.0, comp_zb = 0.0, item = 0.0;
        for (int c = 0; c < NCLS; c++) {
            double cnt = (double)g_counts[c];
            double w = (cnt + 1e-8) / (2.0 * (double)N_ROWS);
            double ldz  = g_logdet[c];
            double ldzb = g_logdet[10 + c];
            sum_ldz  += ldz;
            sum_ldzb += ldzb;
            comp_z   += w * ldz;
            comp_zb  += w * ldzb;
            item     += 0.5 * g_logdet[20 + c];
        }
        double disc_z  = 0.5 * g_logdet[30];
        double disc_zb = 0.5 * g_logdet[31];
        double t1 = disc_z - comp_z;
        double t2 = disc_zb - comp_zb;
        double term3 = item - 0.25 * sum_ldz - 0.25 * sum_ldzb;
        out[0] = (float)(-(t1 + t2 + term3));
        out[1] = (float)(-t1);
        out[2] = (float)(-t2);
        out[3] = (float)term3;
    }
}

// ---------------- launch ----------------
extern "C" void kernel_launch(void* const* d_in, const int* in_sizes, int n_in,
                              void* d_out, int out_size) {
    const float* Z   = (const float*)d_in[0];
    const float* Zb  = (const float*)d_in[1];
    const int*   lbl = (const int*)d_in[2];
    float* out = (float*)d_out;

    k_setup<<<1, 1024>>>(lbl);
    k_gram<<<dim3(36, 20), 64>>>(Z, Zb);
    k_buildM<<<dim3(DIM, NMAT), 128>>>();

    k_diag64<<<NMAT, 256>>>(0);                        // panel 0 diag + W
    for (int p = 0; p < 7; p++) {
        int kb = p * PNB;
        int nt = 7 - p;
        k_panel<<<dim3(nt + nt * (nt + 1) / 2, NMAT), 64>>>(kb, p == 6 ? 1 : 0);
    }
    k_combine<<<1, 32>>>(out);
}

// round 16
// speedup vs baseline: 1.0095x; 1.0095x over previous
#include <cuda_runtime.h>
#include <math.h>
#include <stdint.h>

#define N_ROWS 8192
#define DIM    512
#define NCLS   10
#define NMAT   32
#define PNB    64

// ---------------- scratch (static device globals; no allocation) ----------------
__device__ int    g_counts[NCLS];
__device__ int    g_offsets[NCLS];
__device__ int    g_sorted[N_ROWS];
__device__ float  g_gram[2 * NCLS][DIM * DIM];
__device__ float  g_M[NMAT][DIM * DIM];
__device__ float  g_P[NMAT][(DIM - PNB) * PNB];
__device__ float  g_W[NMAT][PNB * PNB];
__device__ double g_logdet[NMAT];

// ---------------- fused setup ----------------
__global__ void __launch_bounds__(1024) k_setup(const int* __restrict__ lbl) {
    __shared__ int sc[NCLS], scur[NCLS];
    int tid = threadIdx.x;
    if (tid < NCLS) sc[tid] = 0;
    if (tid < NMAT) g_logdet[tid] = 0.0;
    __syncthreads();
    for (int i = tid; i < N_ROWS; i += 1024) atomicAdd(&sc[lbl[i]], 1);
    __syncthreads();
    if (tid == 0) {
        int acc = 0;
        for (int c = 0; c < NCLS; c++) {
            g_counts[c]  = sc[c];
            g_offsets[c] = acc;
            scur[c] = acc;
            acc += sc[c];
        }
    }
    __syncthreads();
    for (int i = tid; i < N_ROWS; i += 1024) {
        int p = atomicAdd(&scur[lbl[i]], 1);
        g_sorted[p] = i;
    }
}

// ---------------- cp.async helper ----------------
__device__ __forceinline__ void cpa16(uint32_t dst, const void* src, int sz) {
    asm volatile("cp.async.ca.shared.global [%0], [%1], 16, %2;"
                 :: "r"(dst), "l"(src), "r"(sz));
}

// ---------------- per-class Gram (validated) ----------------
__global__ void __launch_bounds__(64) k_gram(const float* __restrict__ Z,
                                             const float* __restrict__ Zb) {
    int m = blockIdx.y;
    int c = m % NCLS;
    const float* src = (m < NCLS) ? Z : Zb;

    int bi = 0, r = blockIdx.x;
    while (r >= bi + 1) { r -= bi + 1; bi++; }
    int bj = r;

    int off = g_offsets[c];
    int cnt = g_counts[c];

    __shared__ __align__(16) float sA[2][32][64];
    __shared__ __align__(16) float sB[2][32][64];

    int tid = threadIdx.x;
    int tx = tid & 7, ty = tid >> 3;
    int q = tid & 15;
    int kbase = tid >> 4;

    uint32_t sA0 = (uint32_t)__cvta_generic_to_shared(&sA[0][0][0]);
    uint32_t sB0 = (uint32_t)__cvta_generic_to_shared(&sB[0][0][0]);

    int nC = (cnt + 31) >> 5;

    auto issue = [&](int ci, int b) {
#pragma unroll
        for (int it = 0; it < 8; it++) {
            int k  = kbase + it * 4;
            int kr = ci * 32 + k;
            const float* pa = src;
            const float* pb = src;
            int sz = 0;
            if (kr < cnt) {
                int row = g_sorted[off + kr];
                const float* rp = src + (size_t)row * DIM;
                pa = rp + bi * 64 + q * 4;
                pb = rp + bj * 64 + q * 4;
                sz = 16;
            }
            uint32_t o = (uint32_t)(((b * 32 + k) * 64 + q * 4) * 4);
            cpa16(sA0 + o, pa, sz);
            cpa16(sB0 + o, pb, sz);
        }
        asm volatile("cp.async.commit_group;");
    };

    float acc[8][8];
#pragma unroll
    for (int i = 0; i < 8; i++)
#pragma unroll
        for (int j = 0; j < 8; j++) acc[i][j] = 0.f;

    if (nC > 0) issue(0, 0);
    for (int ci = 0; ci < nC; ci++) {
        int b = ci & 1;
        asm volatile("cp.async.wait_group 0;" ::: "memory");
        __syncthreads();
        if (ci + 1 < nC) issue(ci + 1, b ^ 1);

#pragma unroll 8
        for (int k = 0; k < 32; k++) {
            float4 a0 = *(const float4*)&sA[b][k][ty * 8];
            float4 a1 = *(const float4*)&sA[b][k][ty * 8 + 4];
            float4 b0 = *(const float4*)&sB[b][k][tx * 8];
            float4 b1 = *(const float4*)&sB[b][k][tx * 8 + 4];
            float aa[8] = {a0.x, a0.y, a0.z, a0.w, a1.x, a1.y, a1.z, a1.w};
            float bb[8] = {b0.x, b0.y, b0.z, b0.w, b1.x, b1.y, b1.z, b1.w};
#pragma unroll
            for (int i = 0; i < 8; i++)
#pragma unroll
                for (int j = 0; j < 8; j++) acc[i][j] += aa[i] * bb[j];
        }
        __syncthreads();
    }

    float* G = g_gram[m];
#pragma unroll
    for (int i = 0; i < 8; i++) {
        int gi = bi * 64 + ty * 8 + i;
        float4 v0 = make_float4(acc[i][0], acc[i][1], acc[i][2], acc[i][3]);
        float4 v1 = make_float4(acc[i][4], acc[i][5], acc[i][6], acc[i][7]);
        int gj = bj * 64 + tx * 8;
        *(float4*)&G[(size_t)gi * DIM + gj]     = v0;
        *(float4*)&G[(size_t)gi * DIM + gj + 4] = v1;
        if (bi != bj) {
#pragma unroll
            for (int j = 0; j < 8; j++)
                G[(size_t)(gj + j) * DIM + gi] = acc[i][j];
        }
    }
}

// ---------------- scaled gram element loader (must match buildM exactly) ----------------
__device__ __forceinline__ float4 scaled_gram4(int m, int row, int col) {
    float4 v;
    if (m < 20) {
        int c = (m < 10) ? m : (m - 10);
        float cnt = (float)g_counts[c];
        float s = 512.f / ((cnt + 1e-8f) * 0.5f);
        float4 g = *(const float4*)&g_gram[m][row * DIM + col];
        v = make_float4(s * g.x, s * g.y, s * g.z, s * g.w);
    } else if (m < 30) {
        int c = m - 20;
        float cnt = (float)g_counts[c];
        float s = 512.f / (2.f * cnt * 0.5f);
        float4 g1 = *(const float4*)&g_gram[c][row * DIM + col];
        float4 g2 = *(const float4*)&g_gram[10 + c][row * DIM + col];
        v = make_float4(s * (g1.x + g2.x), s * (g1.y + g2.y),
                        s * (g1.z + g2.z), s * (g1.w + g2.w));
    } else {
        int base = (m == 30) ? 0 : 10;
        float4 s4 = make_float4(0.f, 0.f, 0.f, 0.f);
        for (int c = 0; c < NCLS; c++) {
            float4 g = *(const float4*)&g_gram[base + c][row * DIM + col];
            s4.x += g.x; s4.y += g.y; s4.z += g.z; s4.w += g.w;
        }
        const float s = 0.125f;
        v = make_float4(s * s4.x, s * s4.y, s * s4.z, s * s4.w);
    }
    return v;
}

// ---------------- fused buildM (y<32) + panel-0 diag (y==32, x<32) ----------------
// buildM: 256 thr, 2 rows per block, grid.x = 256.
// diag blocks read g_gram directly (independent of buildM in the same launch).
__global__ void __launch_bounds__(256) k_buildMD() {
    __shared__ float  sL[64][65];
    __shared__ __align__(16) float sW[64][68];
    __shared__ float  sT[32][33];
    __shared__ float  sColB[2][64];
    __shared__ float  sInv[64];
    __shared__ double sRed[8];

    int tid = threadIdx.x;

    if (blockIdx.y < NMAT) {
        // ================= buildM role =================
        int m   = blockIdx.y;
        int row = blockIdx.x * 2 + (tid >> 7);
        int col = (tid & 127) * 4;

        float4 v = scaled_gram4(m, row, col);
        if (row >= col && row < col + 4) {
            if (row == col)          v.x += 1.f;
            else if (row == col + 1) v.y += 1.f;
            else if (row == col + 2) v.z += 1.f;
            else                     v.w += 1.f;
        }
        *(float4*)&g_M[m][row * DIM + col] = v;
        return;
    }

    // ================= panel-0 diag role (R13-validated algorithm) =================
    if (blockIdx.x >= NMAT) return;
    int m = blockIdx.x;

    int r  = tid & 63;
    int s  = tid >> 6;
    int c0 = s * 16;

    // build own 16-col strip of the 64x64 corner: I + scaled gram
    float a[16];
#pragma unroll
    for (int t4 = 0; t4 < 4; t4++) {
        float4 v = scaled_gram4(m, r, c0 + t4 * 4);
        a[t4*4+0]=v.x; a[t4*4+1]=v.y; a[t4*4+2]=v.z; a[t4*4+3]=v.w;
    }
    if (r >= c0 && r < c0 + 16) a[r - c0] += 1.f;

    if (s == 0) sColB[0][r] = a[0];
    __syncthreads();

    double lsum = 0.0;
    for (int j = 0; j < 64; j++) {
        int par = j & 1;
        float d  = sColB[par][j];
        float rs = rsqrtf(d);
        float t2 = sColB[par][r] * (rs * rs);
#pragma unroll
        for (int i = 0; i < 16; i++) {
            int c = c0 + i;
            if (c > j) a[i] -= t2 * sColB[par][c];
        }
        if (s == (j >> 4)) sL[r][j] = sColB[par][r] * rs;
        if (j < 63 && s == ((j + 1) >> 4)) sColB[par ^ 1][r] = a[(j + 1) & 15];
        if (tid == j) { sInv[j] = rs; lsum = (double)logf(d); }
        __syncthreads();
    }

#pragma unroll
    for (int o = 16; o; o >>= 1) lsum += __shfl_xor_sync(0xffffffffu, lsum, o);
    if ((tid & 31) == 0) sRed[tid >> 5] = lsum;
    __syncthreads();
    if (tid == 0) {
        double s2 = 0.0;
        for (int i = 0; i < 8; i++) s2 += sRed[i];
        g_logdet[m] += s2;
    }

    for (int e = tid; e < 64 * 68; e += 256)
        ((float*)sW)[e] = 0.f;
    __syncthreads();

    if (tid < 64) {
        int base = (tid < 32) ? 0 : 32;
        int c = tid & 31;
        float w[32], prt[32];
#pragma unroll
        for (int t = 0; t < 32; t++) prt[t] = 0.f;
#pragma unroll
        for (int j = 0; j < 32; j++) {
            float v;
            if (j < c)       v = 0.f;
            else if (j == c) v = sInv[base + j];
            else             v = -prt[j] * sInv[base + j];
            w[j] = v;
#pragma unroll
            for (int j2 = 0; j2 < 32; j2++)
                if (j2 > j) prt[j2] += sL[base + j2][base + j] * v;
        }
#pragma unroll
        for (int j = 0; j < 32; j++) sW[base + j][base + c] = w[j];
    }
    __syncthreads();

    for (int e = tid; e < 1024; e += 256) {
        int i = e >> 5, j = e & 31;
        float acc = 0.f;
#pragma unroll
        for (int t = 0; t < 32; t++) acc += sL[32 + i][t] * sW[t][j];
        sT[i][j] = acc;
    }
    __syncthreads();

    for (int e = tid; e < 1024; e += 256) {
        int i = e >> 5, j = e & 31;
        float acc = 0.f;
#pragma unroll
        for (int t = 0; t < 32; t++) acc += sW[32 + i][32 + t] * sT[t][j];
        sW[32 + i][j] = -acc;
    }
    __syncthreads();

#pragma unroll
    for (int it = 0; it < 4; it++) {
        int t = tid + it * 256;
        int rr = t >> 4, q = t & 15;
        *(float4*)(g_W[m] + rr * PNB + q * 4) = *(const float4*)&sW[rr][q * 4];
    }
}

// ---------------- TRSM as GEMM: P = A21 * W^T (validated) ----------------
__global__ void __launch_bounds__(64) k_trsmW(int kb) {
    int m  = blockIdx.y;
    int ti = blockIdx.x;

    __shared__ float sA[64][PNB + 1];
    __shared__ float sB[64][PNB + 1];

    const float* M = g_M[m];
    const float* W = g_W[m];
    int tid = threadIdx.x;
    int tx = tid & 7, ty = tid >> 3;

#pragma unroll
    for (int it = 0; it < 16; it++) {
        int t = tid + it * 64;
        int row = t >> 4, q = t & 15;
        float4 va = *(const float4*)(M + (size_t)(kb + PNB + ti * 64 + row) * DIM + kb + q * 4);
        sA[row][q*4+0]=va.x; sA[row][q*4+1]=va.y; sA[row][q*4+2]=va.z; sA[row][q*4+3]=va.w;
        float4 vb = *(const float4*)(W + row * PNB + q * 4);
        sB[row][q*4+0]=vb.x; sB[row][q*4+1]=vb.y; sB[row][q*4+2]=vb.z; sB[row][q*4+3]=vb.w;
    }
    __syncthreads();

    float acc[8][8];
#pragma unroll
    for (int i = 0; i < 8; i++)
#pragma unroll
        for (int j = 0; j < 8; j++) acc[i][j] = 0.f;

#pragma unroll 4
    for (int k = 0; k < PNB; k++) {
        float aa[8], bb[8];
#pragma unroll
        for (int i = 0; i < 8; i++) aa[i] = sA[ty * 8 + i][k];
#pragma unroll
        for (int j = 0; j < 8; j++) bb[j] = sB[tx * 8 + j][k];
#pragma unroll
        for (int i = 0; i < 8; i++)
#pragma unroll
            for (int j = 0; j < 8; j++) acc[i][j] += aa[i] * bb[j];
    }

    float* P = g_P[m];
#pragma unroll
    for (int i = 0; i < 8; i++) {
        int rl = ti * 64 + ty * 8 + i;
        float* pp = P + (size_t)rl * PNB + tx * 8;
        *(float4*)pp       = make_float4(acc[i][0], acc[i][1], acc[i][2], acc[i][3]);
        *(float4*)(pp + 4) = make_float4(acc[i][4], acc[i][5], acc[i][6], acc[i][7]);
    }
}

// ---------------- SYRK + embedded next-panel diag (R14 validated) ----------------
__global__ void __launch_bounds__(64) k_syrkD(int kb, int last) {
    __shared__ __align__(16) float pool[9984];
    float (*sA)[65] = (float(*)[65])pool;
    float (*sB)[65] = (float(*)[65])(pool + 4160);

    int m = blockIdx.y;
    int ti = 0, rr = blockIdx.x;
    while (rr >= ti + 1) { rr -= ti + 1; ti++; }
    int tj = rr;

    const float* P = g_P[m];
    float* M = g_M[m];
    int tid = threadIdx.x;
    int tx = tid & 7, ty = tid >> 3;

#pragma unroll
    for (int it = 0; it < 16; it++) {
        int t = tid + it * 64;
        int row = t >> 4, q = t & 15;
        int ra = ti * 64 + row;
        float4 va = *(const float4*)(P + (size_t)ra * PNB + q * 4);
        sA[row][q*4+0]=va.x; sA[row][q*4+1]=va.y; sA[row][q*4+2]=va.z; sA[row][q*4+3]=va.w;
        int rb = tj * 64 + row;
        float4 vb = *(const float4*)(P + (size_t)rb * PNB + q * 4);
        sB[row][q*4+0]=vb.x; sB[row][q*4+1]=vb.y; sB[row][q*4+2]=vb.z; sB[row][q*4+3]=vb.w;
    }
    __syncthreads();

    float acc[8][8];
#pragma unroll
    for (int i = 0; i < 8; i++)
#pragma unroll
        for (int j = 0; j < 8; j++) acc[i][j] = 0.f;

#pragma unroll 4
    for (int k = 0; k < PNB; k++) {
        float aa[8], bb[8];
#pragma unroll
        for (int i = 0; i < 8; i++) aa[i] = sA[ty * 8 + i][k];
#pragma unroll
        for (int j = 0; j < 8; j++) bb[j] = sB[tx * 8 + j][k];
#pragma unroll
        for (int i = 0; i < 8; i++)
#pragma unroll
            for (int j = 0; j < 8; j++) acc[i][j] += aa[i] * bb[j];
    }

    int base = kb + PNB;

    if (blockIdx.x != 0) {
        if (ti != tj) {
#pragma unroll
            for (int i = 0; i < 8; i++) {
                int rl = ti * 64 + ty * 8 + i;
                float* mp = M + (size_t)(base + rl) * DIM + base + tj * 64 + tx * 8;
                float4 v0 = *(float4*)mp;
                float4 v1 = *(float4*)(mp + 4);
                v0.x -= acc[i][0]; v0.y -= acc[i][1]; v0.z -= acc[i][2]; v0.w -= acc[i][3];
                v1.x -= acc[i][4]; v1.y -= acc[i][5]; v1.z -= acc[i][6]; v1.w -= acc[i][7];
                *(float4*)mp = v0;
                *(float4*)(mp + 4) = v1;
            }
        } else {
#pragma unroll
            for (int i = 0; i < 8; i++) {
                int rl = ti * 64 + ty * 8 + i;
                float* mp = M + (size_t)(base + rl) * DIM + base;
#pragma unroll
                for (int j = 0; j < 8; j++) {
                    int cl = tj * 64 + tx * 8 + j;
                    if (cl <= rl) mp[cl] -= acc[i][j];
                }
            }
        }
        return;
    }

    // ============ block 0: diag tile update into SMEM + factor ============
    __syncthreads();
    float (*sD)[65] = (float(*)[65])pool;
#pragma unroll
    for (int i = 0; i < 8; i++) {
        int rl = ty * 8 + i;
        const float* mp = M + (size_t)(base + rl) * DIM + base;
#pragma unroll
        for (int j = 0; j < 8; j++) {
            int cl = tx * 8 + j;
            if (cl <= rl) sD[rl][cl] = mp[cl] - acc[i][j];
        }
    }
    __syncthreads();

    int r = tid;
    float a[64];
#pragma unroll
    for (int c = 0; c < 64; c++) a[c] = sD[r][c];
    __syncthreads();

    float* sColBuf = pool + 9760;
    float* sInv    = pool + 9888;
    double* sRed   = (double*)(pool + 9952);

    double lsum = 0.0;
#pragma unroll
    for (int j = 0; j < 64; j++) {
        float* sCol = sColBuf + (j & 1) * 64;
        sCol[r] = a[j];
        __syncthreads();
        float d   = sCol[j];
        float inv = rsqrtf(d);
        if (r == j) { lsum = (double)logf(d); sInv[j] = inv; }
        a[j] *= inv;
        float t = a[j] * inv;
#pragma unroll
        for (int c = j + 1; c < 64; c++)
            a[c] -= t * sCol[c];
    }

#pragma unroll
    for (int o = 16; o; o >>= 1) lsum += __shfl_xor_sync(0xffffffffu, lsum, o);
    if ((r & 31) == 0) sRed[r >> 5] = lsum;
    __syncthreads();
    if (r == 0) g_logdet[m] += sRed[0] + sRed[1];

    if (last) return;

    float (*sL)[68] = (float(*)[68])pool;
    float (*sW)[68] = (float(*)[68])(pool + 4352);
    float (*sT)[33] = (float(*)[33])(pool + 8704);
#pragma unroll
    for (int t4 = 0; t4 < 16; t4++)
        *(float4*)&sL[r][t4*4] =
            make_float4(a[t4*4], a[t4*4+1], a[t4*4+2], a[t4*4+3]);
    __syncthreads();

    {
        int base2 = (r < 32) ? 0 : 32;
        int c = r & 31;
        float w[32], prt[32];
#pragma unroll
        for (int t = 0; t < 32; t++) prt[t] = 0.f;
#pragma unroll
        for (int j = 0; j < 32; j++) {
            float v;
            if (j < c)       v = 0.f;
            else if (j == c) v = sInv[base2 + j];
            else             v = -prt[j] * sInv[base2 + j];
            w[j] = v;
#pragma unroll
            for (int j2 = 0; j2 < 32; j2++)
                if (j2 > j) prt[j2] += sL[base2 + j2][base2 + j] * v;
        }
#pragma unroll
        for (int j = 0; j < 32; j++) sW[base2 + j][base2 + c] = w[j];
    }
    if (r < 32) {
        float4 z = make_float4(0.f, 0.f, 0.f, 0.f);
#pragma unroll
        for (int t4 = 8; t4 < 16; t4++) *(float4*)&sW[r][t4*4] = z;
    }
    __syncthreads();

    for (int e = r; e < 1024; e += 64) {
        int i = e >> 5, j = e & 31;
        float s = 0.f;
#pragma unroll
        for (int t = 0; t < 32; t++) s += sL[32 + i][t] * sW[t][j];
        sT[i][j] = s;
    }
    __syncthreads();

    for (int e = r; e < 1024; e += 64) {
        int i = e >> 5, j = e & 31;
        float s = 0.f;
#pragma unroll
        for (int t = 0; t < 32; t++) s += sW[32 + i][32 + t] * sT[t][j];
        sW[32 + i][j] = -s;
    }
    __syncthreads();

    {
        float* wp = g_W[m] + r * PNB;
#pragma unroll
        for (int t4 = 0; t4 < 16; t4++)
            *(float4*)(wp + t4 * 4) = *(const float4*)&sW[r][t4*4];
    }
}

// ---------------- combine into the 4 outputs ----------------
__global__ void k_combine(float* __restrict__ out) {
    if (threadIdx.x == 0) {
        double sum_ldz = 0.0, sum_ldzb = 0.0, comp_z = 0.0, comp_zb = 0.0, item = 0.0;
        for (int c = 0; c < NCLS; c++) {
            double cnt = (double)g_counts[c];
            double w = (cnt + 1e-8) / (2.0 * (double)N_ROWS);
            double ldz  = g_logdet[c];
            double ldzb = g_logdet[10 + c];
            sum_ldz  += ldz;
            sum_ldzb += ldzb;
            comp_z   += w * ldz;
            comp_zb  += w * ldzb;
            item     += 0.5 * g_logdet[20 + c];
        }
        double disc_z  = 0.5 * g_logdet[30];
        double disc_zb = 0.5 * g_logdet[31];
        double t1 = disc_z - comp_z;
        double t2 = disc_zb - comp_zb;
        double term3 = item - 0.25 * sum_ldz - 0.25 * sum_ldzb;
        out[0] = (float)(-(t1 + t2 + term3));
        out[1] = (float)(-t1);
        out[2] = (float)(-t2);
        out[3] = (float)term3;
    }
}

// ---------------- launch ----------------
extern "C" void kernel_launch(void* const* d_in, const int* in_sizes, int n_in,
                              void* d_out, int out_size) {
    const float* Z   = (const float*)d_in[0];
    const float* Zb  = (const float*)d_in[1];
    const int*   lbl = (const int*)d_in[2];
    float* out = (float*)d_out;

    k_setup<<<1, 1024>>>(lbl);
    k_gram<<<dim3(36, 20), 64>>>(Z, Zb);
    k_buildMD<<<dim3(256, NMAT + 1), 256>>>();     // buildM + panel-0 diag fused
    for (int p = 0; p < 7; p++) {
        int kb = p * PNB;
        int nt = 7 - p;
        k_trsmW<<<dim3(nt, NMAT), 64>>>(kb);
        k_syrkD<<<dim3(nt * (nt + 1) / 2, NMAT), 64>>>(kb, p == 6 ? 1 : 0);
    }
    k_combine<<<1, 32>>>(out);
}

// round 17
// speedup vs baseline: 1.0518x; 1.0419x over previous
#include <cuda_runtime.h>
#include <math.h>
#include <stdint.h>

#define N_ROWS 8192
#define DIM    512
#define NCLS   10
#define NMAT   32
#define PNB    64
#define FINRES 192
#define CNB    16

// ---------------- scratch (static device globals; no allocation) ----------------
__device__ int    g_counts[NCLS];
__device__ int    g_offsets[NCLS];
__device__ int    g_sorted[N_ROWS];
__device__ float  g_gram[2 * NCLS][DIM * DIM];
__device__ float  g_M[NMAT][DIM * DIM];
__device__ float  g_P[NMAT][(DIM - PNB) * PNB];
__device__ float  g_W[NMAT][PNB * PNB];
__device__ double g_logdet[NMAT];

// ---------------- fused setup ----------------
__global__ void __launch_bounds__(1024) k_setup(const int* __restrict__ lbl) {
    __shared__ int sc[NCLS], scur[NCLS];
    int tid = threadIdx.x;
    if (tid < NCLS) sc[tid] = 0;
    if (tid < NMAT) g_logdet[tid] = 0.0;
    __syncthreads();
    for (int i = tid; i < N_ROWS; i += 1024) atomicAdd(&sc[lbl[i]], 1);
    __syncthreads();
    if (tid == 0) {
        int acc = 0;
        for (int c = 0; c < NCLS; c++) {
            g_counts[c]  = sc[c];
            g_offsets[c] = acc;
            scur[c] = acc;
            acc += sc[c];
        }
    }
    __syncthreads();
    for (int i = tid; i < N_ROWS; i += 1024) {
        int p = atomicAdd(&scur[lbl[i]], 1);
        g_sorted[p] = i;
    }
}

// ---------------- cp.async helper ----------------
__device__ __forceinline__ void cpa16(uint32_t dst, const void* src, int sz) {
    asm volatile("cp.async.ca.shared.global [%0], [%1], 16, %2;"
                 :: "r"(dst), "l"(src), "r"(sz));
}

// ---------------- per-class Gram (validated) ----------------
__global__ void __launch_bounds__(64) k_gram(const float* __restrict__ Z,
                                             const float* __restrict__ Zb) {
    int m = blockIdx.y;
    int c = m % NCLS;
    const float* src = (m < NCLS) ? Z : Zb;

    int bi = 0, r = blockIdx.x;
    while (r >= bi + 1) { r -= bi + 1; bi++; }
    int bj = r;

    int off = g_offsets[c];
    int cnt = g_counts[c];

    __shared__ __align__(16) float sA[2][32][64];
    __shared__ __align__(16) float sB[2][32][64];

    int tid = threadIdx.x;
    int tx = tid & 7, ty = tid >> 3;
    int q = tid & 15;
    int kbase = tid >> 4;

    uint32_t sA0 = (uint32_t)__cvta_generic_to_shared(&sA[0][0][0]);
    uint32_t sB0 = (uint32_t)__cvta_generic_to_shared(&sB[0][0][0]);

    int nC = (cnt + 31) >> 5;

    auto issue = [&](int ci, int b) {
#pragma unroll
        for (int it = 0; it < 8; it++) {
            int k  = kbase + it * 4;
            int kr = ci * 32 + k;
            const float* pa = src;
            const float* pb = src;
            int sz = 0;
            if (kr < cnt) {
                int row = g_sorted[off + kr];
                const float* rp = src + (size_t)row * DIM;
                pa = rp + bi * 64 + q * 4;
                pb = rp + bj * 64 + q * 4;
                sz = 16;
            }
            uint32_t o = (uint32_t)(((b * 32 + k) * 64 + q * 4) * 4);
            cpa16(sA0 + o, pa, sz);
            cpa16(sB0 + o, pb, sz);
        }
        asm volatile("cp.async.commit_group;");
    };

    float acc[8][8];
#pragma unroll
    for (int i = 0; i < 8; i++)
#pragma unroll
        for (int j = 0; j < 8; j++) acc[i][j] = 0.f;

    if (nC > 0) issue(0, 0);
    for (int ci = 0; ci < nC; ci++) {
        int b = ci & 1;
        asm volatile("cp.async.wait_group 0;" ::: "memory");
        __syncthreads();
        if (ci + 1 < nC) issue(ci + 1, b ^ 1);

#pragma unroll 8
        for (int k = 0; k < 32; k++) {
            float4 a0 = *(const float4*)&sA[b][k][ty * 8];
            float4 a1 = *(const float4*)&sA[b][k][ty * 8 + 4];
            float4 b0 = *(const float4*)&sB[b][k][tx * 8];
            float4 b1 = *(const float4*)&sB[b][k][tx * 8 + 4];
            float aa[8] = {a0.x, a0.y, a0.z, a0.w, a1.x, a1.y, a1.z, a1.w};
            float bb[8] = {b0.x, b0.y, b0.z, b0.w, b1.x, b1.y, b1.z, b1.w};
#pragma unroll
            for (int i = 0; i < 8; i++)
#pragma unroll
                for (int j = 0; j < 8; j++) acc[i][j] += aa[i] * bb[j];
        }
        __syncthreads();
    }

    float* G = g_gram[m];
#pragma unroll
    for (int i = 0; i < 8; i++) {
        int gi = bi * 64 + ty * 8 + i;
        float4 v0 = make_float4(acc[i][0], acc[i][1], acc[i][2], acc[i][3]);
        float4 v1 = make_float4(acc[i][4], acc[i][5], acc[i][6], acc[i][7]);
        int gj = bj * 64 + tx * 8;
        *(float4*)&G[(size_t)gi * DIM + gj]     = v0;
        *(float4*)&G[(size_t)gi * DIM + gj + 4] = v1;
        if (bi != bj) {
#pragma unroll
            for (int j = 0; j < 8; j++)
                G[(size_t)(gj + j) * DIM + gi] = acc[i][j];
        }
    }
}

// ---------------- build the 32 matrices M = I + s*G ----------------
__global__ void __launch_bounds__(128) k_buildM() {
    int m   = blockIdx.y;
    int row = blockIdx.x;
    int col = threadIdx.x * 4;

    float4 v;
    if (m < 20) {
        int c = (m < 10) ? m : (m - 10);
        float cnt = (float)g_counts[c];
        float s = 512.f / ((cnt + 1e-8f) * 0.5f);
        float4 g = *(const float4*)&g_gram[m][row * DIM + col];
        v = make_float4(s * g.x, s * g.y, s * g.z, s * g.w);
    } else if (m < 30) {
        int c = m - 20;
        float cnt = (float)g_counts[c];
        float s = 512.f / (2.f * cnt * 0.5f);
        float4 g1 = *(const float4*)&g_gram[c][row * DIM + col];
        float4 g2 = *(const float4*)&g_gram[10 + c][row * DIM + col];
        v = make_float4(s * (g1.x + g2.x), s * (g1.y + g2.y),
                        s * (g1.z + g2.z), s * (g1.w + g2.w));
    } else {
        int base = (m == 30) ? 0 : 10;
        float4 s4 = make_float4(0.f, 0.f, 0.f, 0.f);
        for (int c = 0; c < NCLS; c++) {
            float4 g = *(const float4*)&g_gram[base + c][row * DIM + col];
            s4.x += g.x; s4.y += g.y; s4.z += g.z; s4.w += g.w;
        }
        const float s = 0.125f;
        v = make_float4(s * s4.x, s * s4.y, s * s4.z, s * s4.w);
    }
    if (row >= col && row < col + 4) {
        if (row == col)          v.x += 1.f;
        else if (row == col + 1) v.y += 1.f;
        else if (row == col + 2) v.z += 1.f;
        else                     v.w += 1.f;
    }
    *(float4*)&g_M[m][row * DIM + col] = v;
}

// ---------------- standalone diag (panel 0 only) — R13 validated ----------------
__global__ void __launch_bounds__(256) k_diag64(int kb) {
    int m = blockIdx.x;
    float* M = g_M[m];

    __shared__ float  sL[64][65];
    __shared__ __align__(16) float sW[64][68];
    __shared__ float  sT[32][33];
    __shared__ float  sColB[2][64];
    __shared__ float  sInv[64];
    __shared__ double sRed[8];

    int tid = threadIdx.x;
    int r  = tid & 63;
    int s  = tid >> 6;
    int c0 = s * 16;

    float a[16];
    {
        const float* rp = M + (size_t)(kb + r) * DIM + kb + c0;
#pragma unroll
        for (int t4 = 0; t4 < 4; t4++) {
            float4 v = *(const float4*)(rp + t4 * 4);
            a[t4*4+0]=v.x; a[t4*4+1]=v.y; a[t4*4+2]=v.z; a[t4*4+3]=v.w;
        }
    }
    if (s == 0) sColB[0][r] = a[0];
    __syncthreads();

    double lsum = 0.0;
    for (int j = 0; j < 64; j++) {
        int par = j & 1;
        float d  = sColB[par][j];
        float rs = rsqrtf(d);
        float t2 = sColB[par][r] * (rs * rs);
#pragma unroll
        for (int i = 0; i < 16; i++) {
            int c = c0 + i;
            if (c > j) a[i] -= t2 * sColB[par][c];
        }
        if (s == (j >> 4)) sL[r][j] = sColB[par][r] * rs;
        if (j < 63 && s == ((j + 1) >> 4)) sColB[par ^ 1][r] = a[(j + 1) & 15];
        if (tid == j) { sInv[j] = rs; lsum = (double)logf(d); }
        __syncthreads();
    }

#pragma unroll
    for (int o = 16; o; o >>= 1) lsum += __shfl_xor_sync(0xffffffffu, lsum, o);
    if ((tid & 31) == 0) sRed[tid >> 5] = lsum;
    __syncthreads();
    if (tid == 0) {
        double s2 = 0.0;
        for (int i = 0; i < 8; i++) s2 += sRed[i];
        g_logdet[m] += s2;
    }

    for (int e = tid; e < 64 * 68; e += 256)
        ((float*)sW)[e] = 0.f;
    __syncthreads();

    if (tid < 64) {
        int base = (tid < 32) ? 0 : 32;
        int c = tid & 31;
        float w[32], prt[32];
#pragma unroll
        for (int t = 0; t < 32; t++) prt[t] = 0.f;
#pragma unroll
        for (int j = 0; j < 32; j++) {
            float v;
            if (j < c)       v = 0.f;
            else if (j == c) v = sInv[base + j];
            else             v = -prt[j] * sInv[base + j];
            w[j] = v;
#pragma unroll
            for (int j2 = 0; j2 < 32; j2++)
                if (j2 > j) prt[j2] += sL[base + j2][base + j] * v;
        }
#pragma unroll
        for (int j = 0; j < 32; j++) sW[base + j][base + c] = w[j];
    }
    __syncthreads();

    for (int e = tid; e < 1024; e += 256) {
        int i = e >> 5, j = e & 31;
        float acc = 0.f;
#pragma unroll
        for (int t = 0; t < 32; t++) acc += sL[32 + i][t] * sW[t][j];
        sT[i][j] = acc;
    }
    __syncthreads();

    for (int e = tid; e < 1024; e += 256) {
        int i = e >> 5, j = e & 31;
        float acc = 0.f;
#pragma unroll
        for (int t = 0; t < 32; t++) acc += sW[32 + i][32 + t] * sT[t][j];
        sW[32 + i][j] = -acc;
    }
    __syncthreads();

#pragma unroll
    for (int it = 0; it < 4; it++) {
        int t = tid + it * 256;
        int rr = t >> 4, q = t & 15;
        *(float4*)(g_W[m] + rr * PNB + q * 4) = *(const float4*)&sW[rr][q * 4];
    }
}

// ---------------- TRSM as GEMM: P = A21 * W^T (validated) ----------------
__global__ void __launch_bounds__(64) k_trsmW(int kb) {
    int m  = blockIdx.y;
    int ti = blockIdx.x;

    __shared__ float sA[64][PNB + 1];
    __shared__ float sB[64][PNB + 1];

    const float* M = g_M[m];
    const float* W = g_W[m];
    int tid = threadIdx.x;
    int tx = tid & 7, ty = tid >> 3;

#pragma unroll
    for (int it = 0; it < 16; it++) {
        int t = tid + it * 64;
        int row = t >> 4, q = t & 15;
        float4 va = *(const float4*)(M + (size_t)(kb + PNB + ti * 64 + row) * DIM + kb + q * 4);
        sA[row][q*4+0]=va.x; sA[row][q*4+1]=va.y; sA[row][q*4+2]=va.z; sA[row][q*4+3]=va.w;
        float4 vb = *(const float4*)(W + row * PNB + q * 4);
        sB[row][q*4+0]=vb.x; sB[row][q*4+1]=vb.y; sB[row][q*4+2]=vb.z; sB[row][q*4+3]=vb.w;
    }
    __syncthreads();

    float acc[8][8];
#pragma unroll
    for (int i = 0; i < 8; i++)
#pragma unroll
        for (int j = 0; j < 8; j++) acc[i][j] = 0.f;

#pragma unroll 4
    for (int k = 0; k < PNB; k++) {
        float aa[8], bb[8];
#pragma unroll
        for (int i = 0; i < 8; i++) aa[i] = sA[ty * 8 + i][k];
#pragma unroll
        for (int j = 0; j < 8; j++) bb[j] = sB[tx * 8 + j][k];
#pragma unroll
        for (int i = 0; i < 8; i++)
#pragma unroll
            for (int j = 0; j < 8; j++) acc[i][j] += aa[i] * bb[j];
    }

    float* P = g_P[m];
#pragma unroll
    for (int i = 0; i < 8; i++) {
        int rl = ti * 64 + ty * 8 + i;
        float* pp = P + (size_t)rl * PNB + tx * 8;
        *(float4*)pp       = make_float4(acc[i][0], acc[i][1], acc[i][2], acc[i][3]);
        *(float4*)(pp + 4) = make_float4(acc[i][4], acc[i][5], acc[i][6], acc[i][7]);
    }
}

// ---------------- SYRK + optional embedded next-panel diag (R14 validated) ----------------
// mode 0: block 0 embeds next-panel diag + W (R14 path).
// mode 2: plain SYRK for all blocks (block 0 writes its diagonal tile to M).
__global__ void __launch_bounds__(64) k_syrkD(int kb, int mode) {
    __shared__ __align__(16) float pool[9984];
    float (*sA)[65] = (float(*)[65])pool;
    float (*sB)[65] = (float(*)[65])(pool + 4160);

    int m = blockIdx.y;
    int ti = 0, rr = blockIdx.x;
    while (rr >= ti + 1) { rr -= ti + 1; ti++; }
    int tj = rr;

    const float* P = g_P[m];
    float* M = g_M[m];
    int tid = threadIdx.x;
    int tx = tid & 7, ty = tid >> 3;

#pragma unroll
    for (int it = 0; it < 16; it++) {
        int t = tid + it * 64;
        int row = t >> 4, q = t & 15;
        int ra = ti * 64 + row;
        float4 va = *(const float4*)(P + (size_t)ra * PNB + q * 4);
        sA[row][q*4+0]=va.x; sA[row][q*4+1]=va.y; sA[row][q*4+2]=va.z; sA[row][q*4+3]=va.w;
        int rb = tj * 64 + row;
        float4 vb = *(const float4*)(P + (size_t)rb * PNB + q * 4);
        sB[row][q*4+0]=vb.x; sB[row][q*4+1]=vb.y; sB[row][q*4+2]=vb.z; sB[row][q*4+3]=vb.w;
    }
    __syncthreads();

    float acc[8][8];
#pragma unroll
    for (int i = 0; i < 8; i++)
#pragma unroll
        for (int j = 0; j < 8; j++) acc[i][j] = 0.f;

#pragma unroll 4
    for (int k = 0; k < PNB; k++) {
        float aa[8], bb[8];
#pragma unroll
        for (int i = 0; i < 8; i++) aa[i] = sA[ty * 8 + i][k];
#pragma unroll
        for (int j = 0; j < 8; j++) bb[j] = sB[tx * 8 + j][k];
#pragma unroll
        for (int i = 0; i < 8; i++)
#pragma unroll
            for (int j = 0; j < 8; j++) acc[i][j] += aa[i] * bb[j];
    }

    int base = kb + PNB;

    if (blockIdx.x != 0 || mode == 2) {
        if (ti != tj) {
#pragma unroll
            for (int i = 0; i < 8; i++) {
                int rl = ti * 64 + ty * 8 + i;
                float* mp = M + (size_t)(base + rl) * DIM + base + tj * 64 + tx * 8;
                float4 v0 = *(float4*)mp;
                float4 v1 = *(float4*)(mp + 4);
                v0.x -= acc[i][0]; v0.y -= acc[i][1]; v0.z -= acc[i][2]; v0.w -= acc[i][3];
                v1.x -= acc[i][4]; v1.y -= acc[i][5]; v1.z -= acc[i][6]; v1.w -= acc[i][7];
                *(float4*)mp = v0;
                *(float4*)(mp + 4) = v1;
            }
        } else {
#pragma unroll
            for (int i = 0; i < 8; i++) {
                int rl = ti * 64 + ty * 8 + i;
                float* mp = M + (size_t)(base + rl) * DIM + base;
#pragma unroll
                for (int j = 0; j < 8; j++) {
                    int cl = tj * 64 + tx * 8 + j;
                    if (cl <= rl) mp[cl] -= acc[i][j];
                }
            }
        }
        return;
    }

    // ============ block 0 (mode 0): diag tile update into SMEM + factor ============
    __syncthreads();
    float (*sD)[65] = (float(*)[65])pool;
#pragma unroll
    for (int i = 0; i < 8; i++) {
        int rl = ty * 8 + i;
        const float* mp = M + (size_t)(base + rl) * DIM + base;
#pragma unroll
        for (int j = 0; j < 8; j++) {
            int cl = tx * 8 + j;
            if (cl <= rl) sD[rl][cl] = mp[cl] - acc[i][j];
        }
    }
    __syncthreads();

    int r = tid;
    float a[64];
#pragma unroll
    for (int c = 0; c < 64; c++) a[c] = sD[r][c];
    __syncthreads();

    float* sColBuf = pool + 9760;
    float* sInv    = pool + 9888;
    double* sRed   = (double*)(pool + 9952);

    double lsum = 0.0;
#pragma unroll
    for (int j = 0; j < 64; j++) {
        float* sCol = sColBuf + (j & 1) * 64;
        sCol[r] = a[j];
        __syncthreads();
        float d   = sCol[j];
        float inv = rsqrtf(d);
        if (r == j) { lsum = (double)logf(d); sInv[j] = inv; }
        a[j] *= inv;
        float t = a[j] * inv;
#pragma unroll
        for (int c = j + 1; c < 64; c++)
            a[c] -= t * sCol[c];
    }

#pragma unroll
    for (int o = 16; o; o >>= 1) lsum += __shfl_xor_sync(0xffffffffu, lsum, o);
    if ((r & 31) == 0) sRed[r >> 5] = lsum;
    __syncthreads();
    if (r == 0) g_logdet[m] += sRed[0] + sRed[1];

    float (*sL)[68] = (float(*)[68])pool;
    float (*sW)[68] = (float(*)[68])(pool + 4352);
    float (*sT)[33] = (float(*)[33])(pool + 8704);
#pragma unroll
    for (int t4 = 0; t4 < 16; t4++)
        *(float4*)&sL[r][t4*4] =
            make_float4(a[t4*4], a[t4*4+1], a[t4*4+2], a[t4*4+3]);
    __syncthreads();

    {
        int base2 = (r < 32) ? 0 : 32;
        int c = r & 31;
        float w[32], prt[32];
#pragma unroll
        for (int t = 0; t < 32; t++) prt[t] = 0.f;
#pragma unroll
        for (int j = 0; j < 32; j++) {
            float v;
            if (j < c)       v = 0.f;
            else if (j == c) v = sInv[base2 + j];
            else             v = -prt[j] * sInv[base2 + j];
            w[j] = v;
#pragma unroll
            for (int j2 = 0; j2 < 32; j2++)
                if (j2 > j) prt[j2] += sL[base2 + j2][base2 + j] * v;
        }
#pragma unroll
        for (int j = 0; j < 32; j++) sW[base2 + j][base2 + c] = w[j];
    }
    if (r < 32) {
        float4 z = make_float4(0.f, 0.f, 0.f, 0.f);
#pragma unroll
        for (int t4 = 8; t4 < 16; t4++) *(float4*)&sW[r][t4*4] = z;
    }
    __syncthreads();

    for (int e = r; e < 1024; e += 64) {
        int i = e >> 5, j = e & 31;
        float s = 0.f;
#pragma unroll
        for (int t = 0; t < 32; t++) s += sL[32 + i][t] * sW[t][j];
        sT[i][j] = s;
    }
    __syncthreads();

    for (int e = r; e < 1024; e += 64) {
        int i = e >> 5, j = e & 31;
        float s = 0.f;
#pragma unroll
        for (int t = 0; t < 32; t++) s += sW[32 + i][32 + t] * sT[t][j];
        sW[32 + i][j] = -s;
    }
    __syncthreads();

    {
        float* wp = g_W[m] + r * PNB;
#pragma unroll
        for (int t4 = 0; t4 < 16; t4++)
            *(float4*)(wp + t4 * 4) = *(const float4*)&sW[r][t4*4];
    }
}

// ---------------- finish last 192x192 block per matrix (R2-validated blocked chol) ----------------
__global__ void __launch_bounds__(256) k_cholfin() {
    int m = blockIdx.x;
    float* M = g_M[m];

    __shared__ float sD[CNB][CNB + 1];
    __shared__ float sInv[CNB];
    __shared__ __align__(16) float sPT[CNB][FINRES];
    __shared__ double sLog;

    int tid = threadIdx.x;
    int tx = tid & 15, ty = tid >> 4;
    if (tid == 0) sLog = 0.0;

    for (int kb = DIM - FINRES; kb < DIM; kb += CNB) {
        if (tid < CNB * CNB) {
            int i = tid / CNB, j = tid % CNB;
            sD[i][j] = M[(size_t)(kb + i) * DIM + kb + j];
        }
        __syncthreads();

        for (int j = 0; j < CNB; j++) {
            if (tid == 0) {
                float d = sD[j][j];
                sLog += (double)logf(d);
                float inv = rsqrtf(d);
                sInv[j] = inv;
                sD[j][j] = d * inv;
            }
            __syncthreads();
            if (tid >= j + 1 && tid < CNB) sD[tid][j] *= sInv[j];
            __syncthreads();
            if (tid < CNB * CNB) {
                int i = tid / CNB, j2 = tid % CNB;
                if (i >= j2 && j2 > j) sD[i][j2] -= sD[i][j] * sD[j2][j];
            }
            __syncthreads();
        }

        int nr = DIM - kb - CNB;
        if (nr == 0) break;

        for (int rr2 = tid; rr2 < nr; rr2 += 256) {
            const float* mr = M + (size_t)(kb + CNB + rr2) * DIM + kb;
            float x[CNB];
            float4 x0 = *(const float4*)(mr + 0);
            float4 x1 = *(const float4*)(mr + 4);
            float4 x2 = *(const float4*)(mr + 8);
            float4 x3 = *(const float4*)(mr + 12);
            x[0]=x0.x; x[1]=x0.y; x[2]=x0.z; x[3]=x0.w;
            x[4]=x1.x; x[5]=x1.y; x[6]=x1.z; x[7]=x1.w;
            x[8]=x2.x; x[9]=x2.y; x[10]=x2.z; x[11]=x2.w;
            x[12]=x3.x; x[13]=x3.y; x[14]=x3.z; x[15]=x3.w;
#pragma unroll
            for (int j = 0; j < CNB; j++) {
                float s = x[j];
#pragma unroll
                for (int t = 0; t < CNB; t++)
                    if (t < j) s -= x[t] * sD[j][t];
                x[j] = s * sInv[j];
            }
#pragma unroll
            for (int j = 0; j < CNB; j++) sPT[j][rr2] = x[j];
        }
        __syncthreads();

        int base = kb + CNB;
        int nT = (nr + 63) / 64;
        for (int ti = 0; ti < nT; ti++) {
            for (int tj = 0; tj <= ti; tj++) {
                int riB = ti * 64 + ty * 4;
                int cjB = tj * 64 + tx * 4;
                bool cok = (cjB < nr);
                float acc[4][4];
#pragma unroll
                for (int i = 0; i < 4; i++) {
                    int ri = riB + i;
                    if (ri < nr && cok) {
                        float4 mv = *(const float4*)&M[(size_t)(base + ri) * DIM + base + cjB];
                        acc[i][0] = mv.x; acc[i][1] = mv.y; acc[i][2] = mv.z; acc[i][3] = mv.w;
                    } else {
                        acc[i][0] = acc[i][1] = acc[i][2] = acc[i][3] = 0.f;
                    }
                }
#pragma unroll
                for (int t = 0; t < CNB; t++) {
                    float4 a = *(const float4*)&sPT[t][riB];
                    float4 b = *(const float4*)&sPT[t][cjB];
                    float aa[4] = {a.x, a.y, a.z, a.w};
                    float bb[4] = {b.x, b.y, b.z, b.w};
#pragma unroll
                    for (int i = 0; i < 4; i++)
#pragma unroll
                        for (int j = 0; j < 4; j++) acc[i][j] -= aa[i] * bb[j];
                }
#pragma unroll
                for (int i = 0; i < 4; i++) {
                    int ri = riB + i;
                    if (ri < nr && cok) {
                        float4 mv = make_float4(acc[i][0], acc[i][1], acc[i][2], acc[i][3]);
                        *(float4*)&M[(size_t)(base + ri) * DIM + base + cjB] = mv;
                    }
                }
            }
        }
        __syncthreads();
    }
    if (tid == 0) g_logdet[m] += sLog;
}

// ---------------- combine into the 4 outputs ----------------
__global__ void k_combine(float* __restrict__ out) {
    if (threadIdx.x == 0) {
        double sum_ldz = 0.0, sum_ldzb = 0.0, comp_z = 0.0, comp_zb = 0.0, item = 0.0;
        for (int c = 0; c < NCLS; c++) {
            double cnt = (double)g_counts[c];
            double w = (cnt + 1e-8) / (2.0 * (double)N_ROWS);
            double ldz  = g_logdet[c];
            double ldzb = g_logdet[10 + c];
            sum_ldz  += ldz;
            sum_ldzb += ldzb;
            comp_z   += w * ldz;
            comp_zb  += w * ldzb;
            item     += 0.5 * g_logdet[20 + c];
        }
        double disc_z  = 0.5 * g_logdet[30];
        double disc_zb = 0.5 * g_logdet[31];
        double t1 = disc_z - comp_z;
        double t2 = disc_zb - comp_zb;
        double term3 = item - 0.25 * sum_ldz - 0.25 * sum_ldzb;
        out[0] = (float)(-(t1 + t2 + term3));
        out[1] = (float)(-t1);
        out[2] = (float)(-t2);
        out[3] = (float)term3;
    }
}

// ---------------- launch ----------------
extern "C" void kernel_launch(void* const* d_in, const int* in_sizes, int n_in,
                              void* d_out, int out_size) {
    const float* Z   = (const float*)d_in[0];
    const float* Zb  = (const float*)d_in[1];
    const int*   lbl = (const int*)d_in[2];
    float* out = (float*)d_out;

    k_setup<<<1, 1024>>>(lbl);
    k_gram<<<dim3(36, 20), 64>>>(Z, Zb);
    k_buildM<<<dim3(DIM, NMAT), 128>>>();

    k_diag64<<<NMAT, 256>>>(0);                        // panel 0 diag + W
    for (int p = 0; p < 5; p++) {
        int kb = p * PNB;
        int nt = 7 - p;
        k_trsmW<<<dim3(nt, NMAT), 64>>>(kb);
        k_syrkD<<<dim3(nt * (nt + 1) / 2, NMAT), 64>>>(kb, p == 4 ? 2 : 0);
    }
    k_cholfin<<<NMAT, 256>>>();                        // last 192x192
    k_combine<<<1, 32>>>(out);
}